// round 16
// baseline (speedup 1.0000x reference)
#include <cuda_runtime.h>
#include <cuda_bf16.h>
#include <cstdint>

#define BATCH 256
#define TOBS  80
#define TTOT  160
#define HID   2048
#define HID4  8192
#define BH    (BATCH * HID)

#define NT      512                  // 16 warps: warp_m (4) x warp_n (4), warp tile 32x32
#define BM      128
#define BN      128
#define NSUP    48                   // super-chunks: K=128 each, 3 products x 16
#define SUB_A1  0
#define SUB_A2  16384
#define SUB_B1  32768
#define SUB_B2  49152
#define SUPER_B 65536                // A 32KB + B 32KB
#define CTRL_B  2048
#define SMEM_DYN (1024 + CTRL_B + 2 * SUPER_B)

// ---------------- persistent device state ----------------
__device__ float          g_c[BH];
__device__ __nv_bfloat16  g_hhi[2 * BH];
__device__ __nv_bfloat16  g_hlo[2 * BH];
__device__ __nv_bfloat16  g_whi[(size_t)HID4 * HID];   // gate-interleaved W_hh hi
__device__ __nv_bfloat16  g_wlo[(size_t)HID4 * HID];   // gate-interleaved W_hh lo

// ---------------- helpers ----------------
static __device__ __forceinline__ uint32_t smem_u32(const void* p) {
    uint32_t a;
    asm("{ .reg .u64 t; cvta.to.shared.u64 t, %1; cvt.u32.u64 %0, t; }" : "=r"(a) : "l"(p));
    return a;
}
static __device__ __forceinline__ void cpa16(uint32_t dst, const void* src) {
    asm volatile("cp.async.cg.shared.global [%0], [%1], 16;" :: "r"(dst), "l"(src) : "memory");
}
static __device__ __forceinline__ void cpa_commit() {
    asm volatile("cp.async.commit_group;" ::: "memory");
}
template <int N>
static __device__ __forceinline__ void cpa_wait() {
    asm volatile("cp.async.wait_group %0;" :: "n"(N) : "memory");
}
static __device__ __forceinline__ void ldsm4(uint32_t* r, uint32_t a) {
    asm volatile("ldmatrix.sync.aligned.m8n8.x4.shared.b16 {%0,%1,%2,%3}, [%4];"
                 : "=r"(r[0]), "=r"(r[1]), "=r"(r[2]), "=r"(r[3]) : "r"(a));
}
static __device__ __forceinline__ void mma16816(float* d, const uint32_t* a, const uint32_t* b) {
    asm volatile("mma.sync.aligned.m16n8k16.row.col.f32.bf16.bf16.f32 "
                 "{%0,%1,%2,%3}, {%4,%5,%6,%7}, {%8,%9}, {%0,%1,%2,%3};"
                 : "+f"(d[0]), "+f"(d[1]), "+f"(d[2]), "+f"(d[3])
                 : "r"(a[0]), "r"(a[1]), "r"(a[2]), "r"(a[3]), "r"(b[0]), "r"(b[1]));
}
static __device__ __forceinline__ float sig_f(float x) {
    return __fdividef(1.0f, 1.0f + __expf(-x));
}
static __device__ __forceinline__ float tanh_f(float x) {
    return __fdividef(2.0f, 1.0f + __expf(-2.0f * x)) - 1.0f;
}

// ---------------- prep kernels ----------------
__global__ void wconv_kernel(const float* __restrict__ W,
                             __nv_bfloat16* __restrict__ whi,
                             __nv_bfloat16* __restrict__ wlo)
{
    int n = blockIdx.x;                  // gate-interleaved row: n = 4*j + g
    int j = n >> 2, g = n & 3;
    const float4* src = (const float4*)(W + ((size_t)g * HID + j) * HID);
    size_t dst = (size_t)n * HID;
#pragma unroll
    for (int r = 0; r < 2; ++r) {
        int q = threadIdx.x + 256 * r;
        float4 v = src[q];
        int k = q * 4;
        float xs[4] = {v.x, v.y, v.z, v.w};
#pragma unroll
        for (int c = 0; c < 4; ++c) {
            __nv_bfloat16 hi = __float2bfloat16(xs[c]);
            whi[dst + k + c] = hi;
            wlo[dst + k + c] = __float2bfloat16(xs[c] - __bfloat162float(hi));
        }
    }
}

__global__ void init_kernel(float* __restrict__ cbuf,
                            __nv_bfloat16* __restrict__ h0hi,
                            __nv_bfloat16* __restrict__ h0lo,
                            float* __restrict__ out,
                            const float* __restrict__ b_lin)
{
    int i = blockIdx.x * blockDim.x + threadIdx.x;
    if (i < BH) {
        cbuf[i] = 0.0f;
        h0hi[i] = __float2bfloat16(0.0f);
        h0lo[i] = __float2bfloat16(0.0f);
    }
    if (i < BATCH * TTOT) out[i] = b_lin[0];
}

// ---------------- fused LSTM step: bf16x3, 128x128 tile, frag-pipelined ----------------
__global__ void __launch_bounds__(NT, 1)
lstm_step(const __nv_bfloat16* __restrict__ Ahi, const __nv_bfloat16* __restrict__ Alo,
          __nv_bfloat16* __restrict__ Ahi_n, __nv_bfloat16* __restrict__ Alo_n,
          float* __restrict__ cbuf,
          const __nv_bfloat16* __restrict__ Whi, const __nv_bfloat16* __restrict__ Wlo,
          const float* __restrict__ W_ih, const float* __restrict__ b_ih,
          const float* __restrict__ b_hh, const float* __restrict__ W_lin,
          float* __restrict__ out,
          const float* __restrict__ xvec, int xstride, int t)
{
    extern __shared__ char smem_raw[];
    const int tid  = threadIdx.x;
    const int wid  = tid >> 5;
    const int lane = tid & 31;
    const int warp_m = wid & 3;          // 4 x 32 rows
    const int warp_n = wid >> 2;         // 4 x 32 cols
    const int m0 = blockIdx.x * BM;
    const int n0 = blockIdx.y * BN;      // gate-interleaved col base
    const int j0 = n0 >> 2;

    uint32_t sb    = smem_u32(smem_raw);
    uint32_t sbase = (sb + 1023) & ~1023u;
    char*    ctrl  = smem_raw + (sbase - sb);
    uint32_t tiles = sbase + CTRL_B;
    float* bias_s = (float*)(ctrl + 0);      // 128
    float* wih_s  = (float*)(ctrl + 512);    // 128
    float* rowsum = (float*)(ctrl + 1024);   // 128
    float* wlin_s = (float*)(ctrl + 1600);   // 32

    if (tid < 128) {
        int j = j0 + (tid >> 2);
        int g = tid & 3;
        bias_s[tid] = b_ih[g * HID + j] + b_hh[g * HID + j];
        wih_s[tid]  = W_ih[g * HID + j];
        rowsum[tid] = 0.0f;
    }
    if (tid < 32) wlin_s[tid] = W_lin[j0 + tid];
    __syncthreads();

    // epilogue row this thread owns; prefetch x input now
    const bool oddl = (lane & 1);
    const int rloc0 = warp_m * 32 + (lane >> 2) + (oddl ? 8 : 0);
    float xin[2];
#pragma unroll
    for (int mf = 0; mf < 2; ++mf)
        xin[mf] = xvec[(size_t)(m0 + rloc0 + mf * 16) * xstride];

    // ---- hoisted load addressing: 8 slices (4 A, 4 B) of one super-chunk ----
    // A: 2 subtiles x 1024 16B-units; 512 thr -> 2 iters per subtile. B same.
    uint32_t swS[8];                     // smem offset (incl subtile base)
    uint32_t goS[8];                     // global byte offset (incl m0/n0 row, +128 for sub2)
#pragma unroll
    for (int i = 0; i < 8; ++i) {
        int isB  = (i >> 2) & 1;         // 0: A, 1: B
        int sub  = (i >> 1) & 1;         // subtile (K 0..63 / 64..127)
        int it   = i & 1;                // iteration within subtile
        int q    = tid + NT * it;
        int row  = q >> 3;
        int cb   = (q & 7) * 16;
        uint32_t sw = (uint32_t)(row * 128 + (cb ^ ((row & 7) * 16)));
        swS[i] = sw + (uint32_t)(isB ? (sub ? SUB_B2 : SUB_B1) : (sub ? SUB_A2 : SUB_A1));
        int base = isB ? n0 : m0;
        goS[i] = (uint32_t)(((base + row) * HID) * 2 + cb + sub * 128);
    }

    float acc[2][4][4];
#pragma unroll
    for (int i = 0; i < 2; ++i)
#pragma unroll
        for (int jf = 0; jf < 4; ++jf)
#pragma unroll
            for (int kf = 0; kf < 4; ++kf) acc[i][jf][kf] = 0.0f;

    // ldmatrix addressing (SW128: xor (row&7)*16, row-invariant per lane)
    const int xm = (lane & 7) * 16;
    int arow[2], brow[2];
#pragma unroll
    for (int mf = 0; mf < 2; ++mf)
        arow[mf] = (warp_m * 32 + mf * 16 + (lane & 15)) * 128;
#pragma unroll
    for (int q = 0; q < 2; ++q)
        brow[q] = (warp_n * 32 + q * 16 + (lane & 7) + ((lane & 16) ? 8 : 0)) * 128;
    const int acoladd = (lane & 16) ? 16 : 0;
    const int bcoladd = (lane & 8) ? 16 : 0;

    // per-k-step frag loader: s in 0..7 (subtile = s>>2, kk = s&3)
    auto load_frags = [&](uint32_t st, int s, uint32_t (*a)[4], uint32_t (*b)[4]) {
        uint32_t sta = st + ((s < 4) ? SUB_A1 : SUB_A2);
        uint32_t stb = st + ((s < 4) ? SUB_B1 : SUB_B2);
        int colA = (s & 3) * 32 + acoladd;
        int colB = (s & 3) * 32 + bcoladd;
#pragma unroll
        for (int mf = 0; mf < 2; ++mf)
            ldsm4(a[mf], sta + arow[mf] + (uint32_t)(colA ^ xm));
#pragma unroll
        for (int q = 0; q < 2; ++q)
            ldsm4(b[q], stb + brow[q] + (uint32_t)(colB ^ xm));
    };

    auto do_mmas = [&](uint32_t (*a)[4], uint32_t (*b)[4]) {
#pragma unroll
        for (int mf = 0; mf < 2; ++mf) {
#pragma unroll
            for (int nf = 0; nf < 4; ++nf) {
                const uint32_t bp[2] = { b[nf >> 1][(nf & 1) * 2],
                                         b[nf >> 1][(nf & 1) * 2 + 1] };
                mma16816(acc[mf][nf], a[mf], bp);
            }
        }
    };

    const char* AhiB = (const char*)Ahi;
    const char* AloB = (const char*)Alo;
    const char* WhiB = (const char*)Whi;
    const char* WloB = (const char*)Wlo;

    // Prologue: super-chunk 0 (Ahi x Whi) into stage 0
#pragma unroll
    for (int i = 0; i < 8; ++i)
        cpa16(tiles + swS[i], ((i < 4) ? AhiB : WhiB) + goS[i]);
    cpa_commit();

    uint32_t afr[2][2][4], bfr[2][2][4];   // double-buffered fragments

    for (int c = 0; c < NSUP; ++c) {
        cpa_wait<0>();
        __syncthreads();

        const int cn = c + 1;
        const bool have_next = (cn < NSUP);
        const int p = cn >> 4;                 // 0: AhiWhi, 1: AhiWlo, 2: AloWhi
        const char* Ab = (p == 2) ? AloB : AhiB;
        const char* Bb = (p == 1) ? WloB : WhiB;
        const uint32_t stn = tiles + (uint32_t)(cn & 1) * SUPER_B;
        const uint32_t koffB = (uint32_t)(cn & 15) * 256;

        uint32_t st = tiles + (uint32_t)(c & 1) * SUPER_B;

        // software-pipelined 8 k-steps: LDSM(s+1) + one cp.async slice per step
        load_frags(st, 0, afr[0], bfr[0]);
#pragma unroll
        for (int s = 0; s < 8; ++s) {
            const int cur = s & 1;
            if (s < 7) load_frags(st, s + 1, afr[cur ^ 1], bfr[cur ^ 1]);
            if (have_next)
                cpa16(stn + swS[s], ((s < 4) ? Ab : Bb) + goS[s] + koffB);
            do_mmas(afr[cur], bfr[cur]);
        }
        cpa_commit();
    }

    // ---- epilogue: gate exchange + LSTM cell + prediction ----
    const int slot = (lane >> 1) & 1;

    // batch-prefetch c_prev (8 values, MLP overlap)
    float cprev[2][4];
#pragma unroll
    for (int mf = 0; mf < 2; ++mf) {
        const int m = m0 + rloc0 + mf * 16;
#pragma unroll
        for (int nf = 0; nf < 4; ++nf) {
            const int jl = warp_n * 8 + nf * 2 + slot;
            cprev[mf][nf] = cbuf[(size_t)m * HID + (j0 + jl)];
        }
    }

#pragma unroll
    for (int mf = 0; mf < 2; ++mf) {
        const int rloc = rloc0 + mf * 16;
        const int m = m0 + rloc;
        float predp = 0.0f;
#pragma unroll
        for (int nf = 0; nf < 4; ++nf) {
            float c0 = acc[mf][nf][0], c1 = acc[mf][nf][1];
            float c2 = acc[mf][nf][2], c3 = acc[mf][nf][3];
            float t0 = __shfl_xor_sync(0xffffffffu, c0, 1);
            float t1 = __shfl_xor_sync(0xffffffffu, c1, 1);
            float t2 = __shfl_xor_sync(0xffffffffu, c2, 1);
            float t3 = __shfl_xor_sync(0xffffffffu, c3, 1);
            float gi, gf, gg, go;
            if (!oddl) { gi = c0; gf = c1; gg = t0; go = t1; }
            else       { gi = t2; gf = t3; gg = c2; go = c3; }

            const int jl = warp_n * 8 + nf * 2 + slot;
            const int nb = jl * 4;
            gi += bias_s[nb + 0] + xin[mf] * wih_s[nb + 0];
            gf += bias_s[nb + 1] + xin[mf] * wih_s[nb + 1];
            gg += bias_s[nb + 2] + xin[mf] * wih_s[nb + 2];
            go += bias_s[nb + 3] + xin[mf] * wih_s[nb + 3];

            const size_t off = (size_t)m * HID + (j0 + jl);
            float cn = sig_f(gf) * cprev[mf][nf] + sig_f(gi) * tanh_f(gg);
            cbuf[off] = cn;
            float hn = sig_f(go) * tanh_f(cn);

            __nv_bfloat16 hi = __float2bfloat16(hn);
            Ahi_n[off] = hi;
            Alo_n[off] = __float2bfloat16(hn - __bfloat162float(hi));
            predp += hn * wlin_s[jl];
        }
        atomicAdd(&rowsum[rloc], predp);
    }
    __syncthreads();
    if (tid < 128)
        atomicAdd(&out[(size_t)(m0 + tid) * TTOT + t], rowsum[tid]);
}

// ---------------- host launch ----------------
extern "C" void kernel_launch(void* const* d_in, const int* in_sizes, int n_in,
                              void* d_out, int out_size) {
    const float* x     = (const float*)d_in[0];
    const float* W_ih  = (const float*)d_in[1];
    const float* W_hh  = (const float*)d_in[2];
    const float* b_ih  = (const float*)d_in[3];
    const float* b_hh  = (const float*)d_in[4];
    const float* W_lin = (const float*)d_in[5];
    const float* b_lin = (const float*)d_in[6];
    float* out = (float*)d_out;

    float *cbuf;
    __nv_bfloat16 *hhi, *hlo, *whi, *wlo;
    cudaGetSymbolAddress((void**)&cbuf, g_c);
    cudaGetSymbolAddress((void**)&hhi,  g_hhi);
    cudaGetSymbolAddress((void**)&hlo,  g_hlo);
    cudaGetSymbolAddress((void**)&whi,  g_whi);
    cudaGetSymbolAddress((void**)&wlo,  g_wlo);

    cudaFuncSetAttribute(lstm_step, cudaFuncAttributeMaxDynamicSharedMemorySize, SMEM_DYN);

    wconv_kernel<<<HID4, 256>>>(W_hh, whi, wlo);
    init_kernel<<<(BH + 255) / 256, 256>>>(cbuf, hhi, hlo, out, b_lin);

    dim3 grid(BATCH / BM, HID4 / BN);

    for (int t = 0; t < TTOT; ++t) {
        const int cur = t & 1;
        const float* xvec;
        int xstride;
        if (t < TOBS) { xvec = x + t;         xstride = TOBS; }
        else          { xvec = out + (t - 1); xstride = TTOT; }

        lstm_step<<<grid, NT, SMEM_DYN>>>(
            hhi + (size_t)cur * BH, hlo + (size_t)cur * BH,
            hhi + (size_t)(1 - cur) * BH, hlo + (size_t)(1 - cur) * BH,
            cbuf, whi, wlo,
            W_ih, b_ih, b_hh, W_lin,
            out, xvec, xstride, t);
    }
}